// round 3
// baseline (speedup 1.0000x reference)
#include <cuda_runtime.h>
#include <math.h>

// Shapes
#define DIMC 192
#define HW   1024
#define BATCH 32
#define GRAMD 18528   // 192*193/2
#define N1 9264
#define N2 4632
#define N3 64

// Scratch (device globals: no allocation allowed in kernel_launch)
__device__ float g_buf[BATCH * GRAMD];
__device__ float h1_buf[BATCH * N1];
__device__ float h2_buf[BATCH * N2];
__device__ float h3_buf[BATCH * N3];

// ---------------------------------------------------------------------------
// Kernel 1: per-sample Gram upper-triangle features.
// grid = (6 tile-pairs, 32 batch), block = 256 threads (16x16), 4x4 micro-tile.
// Tiles of 64x64 over c=192 (3x3 -> 6 upper pairs). K = 1024.
// ---------------------------------------------------------------------------
__global__ void gram_kernel(const float* __restrict__ x, float* __restrict__ g)
{
    __shared__ float As[64][17];
    __shared__ float Bs[64][17];

    const int TI[6] = {0, 0, 0, 1, 1, 2};
    const int TJ[6] = {0, 1, 2, 1, 2, 2};

    int pair = blockIdx.x;
    int b    = blockIdx.y;
    int ti = TI[pair], tj = TJ[pair];

    const float* feat = x + (size_t)b * DIMC * HW;

    int t  = threadIdx.x;
    int ty = t >> 4;      // 0..15
    int tx = t & 15;      // 0..15

    float acc[4][4];
    #pragma unroll
    for (int i = 0; i < 4; i++)
        #pragma unroll
        for (int j = 0; j < 4; j++) acc[i][j] = 0.0f;

    for (int k0 = 0; k0 < HW; k0 += 16) {
        #pragma unroll
        for (int l = 0; l < 4; l++) {
            int idx = t + l * 256;
            int row = idx >> 4;
            int col = idx & 15;
            As[row][col] = feat[(size_t)(ti * 64 + row) * HW + k0 + col];
            Bs[row][col] = feat[(size_t)(tj * 64 + row) * HW + k0 + col];
        }
        __syncthreads();

        #pragma unroll
        for (int kk = 0; kk < 16; kk++) {
            float a[4], bb[4];
            #pragma unroll
            for (int i = 0; i < 4; i++) a[i]  = As[ty * 4 + i][kk];
            #pragma unroll
            for (int j = 0; j < 4; j++) bb[j] = Bs[tx * 4 + j][kk];
            #pragma unroll
            for (int i = 0; i < 4; i++)
                #pragma unroll
                for (int j = 0; j < 4; j++)
                    acc[i][j] += a[i] * bb[j];
        }
        __syncthreads();
    }

    // Write upper-triangle (row-major, incl diag) entries
    #pragma unroll
    for (int i = 0; i < 4; i++) {
        int gi = ti * 64 + ty * 4 + i;
        #pragma unroll
        for (int j = 0; j < 4; j++) {
            int gj = tj * 64 + tx * 4 + j;
            if (gi <= gj) {
                int off = gi * DIMC - (gi * (gi - 1)) / 2 + (gj - gi);
                g[(size_t)b * GRAMD + off] = acc[i][j];
            }
        }
    }
}

// ---------------------------------------------------------------------------
// Generic fused GEMM + bias + leaky-relu:  out[b][n] = lrelu(sum_k in[b][k]*W[n][k] + bias[n])
// M = 32 batches. Warp-split-K: each warp handles 4 n x 8 b, lanes slice K.
// Block = 256 threads = 8 warps = 2 n-groups x 4 b-groups -> block covers 8 n, 32 b.
// grid.x = N/8 (all N divisible by 8). W is streamed from DRAM exactly once.
// ---------------------------------------------------------------------------
template <int K, int N>
__global__ __launch_bounds__(256, 2)
void gemm_lrelu(const float* __restrict__ in, const float* __restrict__ W,
                const float* __restrict__ bias, float* __restrict__ out)
{
    int t    = threadIdx.x;
    int lane = t & 31;
    int wid  = t >> 5;
    int ng   = wid >> 2;          // 0..1
    int bg   = wid & 3;           // 0..3
    int n0   = blockIdx.x * 8 + ng * 4;
    int b0   = bg * 8;

    float acc[4][8];
    #pragma unroll
    for (int i = 0; i < 4; i++)
        #pragma unroll
        for (int j = 0; j < 8; j++) acc[i][j] = 0.0f;

    for (int k0 = 0; k0 < K; k0 += 128) {
        int kk = k0 + lane * 4;
        if (kk < K) {               // K % 4 == 0 for all layers -> full float4 ok
            float4 w4[4], gv[8];
            #pragma unroll
            for (int i = 0; i < 4; i++)
                w4[i] = *reinterpret_cast<const float4*>(W + (size_t)(n0 + i) * K + kk);
            #pragma unroll
            for (int j = 0; j < 8; j++)
                gv[j] = *reinterpret_cast<const float4*>(in + (size_t)(b0 + j) * K + kk);

            #pragma unroll
            for (int i = 0; i < 4; i++) {
                #pragma unroll
                for (int j = 0; j < 8; j++) {
                    acc[i][j] += w4[i].x * gv[j].x;
                    acc[i][j] += w4[i].y * gv[j].y;
                    acc[i][j] += w4[i].z * gv[j].z;
                    acc[i][j] += w4[i].w * gv[j].w;
                }
            }
        }
    }

    // Cross-lane (split-K) butterfly reduction
    #pragma unroll
    for (int off = 16; off > 0; off >>= 1) {
        #pragma unroll
        for (int i = 0; i < 4; i++)
            #pragma unroll
            for (int j = 0; j < 8; j++)
                acc[i][j] += __shfl_xor_sync(0xffffffffu, acc[i][j], off);
    }

    if (lane == 0) {
        #pragma unroll
        for (int i = 0; i < 4; i++) {
            float bi = bias[n0 + i];
            #pragma unroll
            for (int j = 0; j < 8; j++) {
                float v = acc[i][j] + bi;
                v = (v > 0.0f) ? v : 0.01f * v;
                out[(size_t)(b0 + j) * N + (n0 + i)] = v;
            }
        }
    }
}

// ---------------------------------------------------------------------------
// Final: L2-normalize h3 (per-sample over 64), dot with W4, +b4, sigmoid.
// 1 block, 1024 threads, warp per batch sample.
// ---------------------------------------------------------------------------
__global__ void final_kernel(const float* __restrict__ h3, const float* __restrict__ W4,
                             const float* __restrict__ b4, float* __restrict__ out)
{
    int b    = threadIdx.x >> 5;
    int lane = threadIdx.x & 31;

    float v0 = h3[b * 64 + lane * 2];
    float v1 = h3[b * 64 + lane * 2 + 1];

    float ss = v0 * v0 + v1 * v1;
    #pragma unroll
    for (int off = 16; off > 0; off >>= 1)
        ss += __shfl_xor_sync(0xffffffffu, ss, off);

    float denom = fmaxf(sqrtf(ss), 1e-12f);

    float d = v0 * W4[lane * 2] + v1 * W4[lane * 2 + 1];
    #pragma unroll
    for (int off = 16; off > 0; off >>= 1)
        d += __shfl_xor_sync(0xffffffffu, d, off);

    if (lane == 0) {
        float logit = d / denom + b4[0];
        out[b] = 1.0f / (1.0f + expf(-logit));
    }
}

// ---------------------------------------------------------------------------
// Launch
// Inputs (metadata order): x, W1, b1, W2, b2, W3, b3, W4, b4  (all fp32)
// ---------------------------------------------------------------------------
extern "C" void kernel_launch(void* const* d_in, const int* in_sizes, int n_in,
                              void* d_out, int out_size)
{
    const float* x  = (const float*)d_in[0];
    const float* W1 = (const float*)d_in[1];
    const float* b1 = (const float*)d_in[2];
    const float* W2 = (const float*)d_in[3];
    const float* b2 = (const float*)d_in[4];
    const float* W3 = (const float*)d_in[5];
    const float* b3 = (const float*)d_in[6];
    const float* W4 = (const float*)d_in[7];
    const float* b4 = (const float*)d_in[8];
    float* out = (float*)d_out;

    float *g, *h1, *h2, *h3;
    cudaGetSymbolAddress((void**)&g,  g_buf);
    cudaGetSymbolAddress((void**)&h1, h1_buf);
    cudaGetSymbolAddress((void**)&h2, h2_buf);
    cudaGetSymbolAddress((void**)&h3, h3_buf);

    gram_kernel<<<dim3(6, BATCH), 256>>>(x, g);
    gemm_lrelu<GRAMD, N1><<<N1 / 8, 256>>>(g,  W1, b1, h1);
    gemm_lrelu<N1,    N2><<<N2 / 8, 256>>>(h1, W2, b2, h2);
    gemm_lrelu<N2,    N3><<<N3 / 8, 256>>>(h2, W3, b3, h3);
    final_kernel<<<1, 1024>>>(h3, W4, b4, out);
}

// round 4
// speedup vs baseline: 1.1656x; 1.1656x over previous
#include <cuda_runtime.h>
#include <math.h>

// Shapes
#define DIMC 192
#define HW   1024
#define BATCH 32
#define GRAMD 18528   // 192*193/2
#define N1 9264
#define N2 4632
#define N3 64

// Scratch (device globals: no allocation allowed in kernel_launch)
__device__ float g_buf[BATCH * GRAMD];
__device__ float h1_buf[BATCH * N1];
__device__ float h2_buf[BATCH * N2];
__device__ float h3_buf[BATCH * N3];

// Packed f32x2 FMA: d = a*b + d  (two independent fp32 lanes in one issue slot)
__device__ __forceinline__ void ffma2(unsigned long long& d,
                                      unsigned long long a,
                                      unsigned long long b)
{
    asm("fma.rn.f32x2 %0, %1, %2, %0;" : "+l"(d) : "l"(a), "l"(b));
}

__device__ __forceinline__ float fold_f32x2(unsigned long long v)
{
    float2 f = *reinterpret_cast<float2*>(&v);
    return f.x + f.y;
}

// ---------------------------------------------------------------------------
// Kernel 1: per-sample Gram upper-triangle features.
// grid = (6 tile-pairs, 32 batch), block = 256 threads (16x16), 4x4 micro-tile.
// ---------------------------------------------------------------------------
__global__ void gram_kernel(const float* __restrict__ x, float* __restrict__ g)
{
    __shared__ float As[64][17];
    __shared__ float Bs[64][17];

    const int TI[6] = {0, 0, 0, 1, 1, 2};
    const int TJ[6] = {0, 1, 2, 1, 2, 2};

    int pair = blockIdx.x;
    int b    = blockIdx.y;
    int ti = TI[pair], tj = TJ[pair];

    const float* feat = x + (size_t)b * DIMC * HW;

    int t  = threadIdx.x;
    int ty = t >> 4;      // 0..15
    int tx = t & 15;      // 0..15

    float acc[4][4];
    #pragma unroll
    for (int i = 0; i < 4; i++)
        #pragma unroll
        for (int j = 0; j < 4; j++) acc[i][j] = 0.0f;

    for (int k0 = 0; k0 < HW; k0 += 16) {
        #pragma unroll
        for (int l = 0; l < 4; l++) {
            int idx = t + l * 256;
            int row = idx >> 4;
            int col = idx & 15;
            As[row][col] = feat[(size_t)(ti * 64 + row) * HW + k0 + col];
            Bs[row][col] = feat[(size_t)(tj * 64 + row) * HW + k0 + col];
        }
        __syncthreads();

        #pragma unroll
        for (int kk = 0; kk < 16; kk++) {
            float a[4], bb[4];
            #pragma unroll
            for (int i = 0; i < 4; i++) a[i]  = As[ty * 4 + i][kk];
            #pragma unroll
            for (int j = 0; j < 4; j++) bb[j] = Bs[tx * 4 + j][kk];
            #pragma unroll
            for (int i = 0; i < 4; i++)
                #pragma unroll
                for (int j = 0; j < 4; j++)
                    acc[i][j] += a[i] * bb[j];
        }
        __syncthreads();
    }

    #pragma unroll
    for (int i = 0; i < 4; i++) {
        int gi = ti * 64 + ty * 4 + i;
        #pragma unroll
        for (int j = 0; j < 4; j++) {
            int gj = tj * 64 + tx * 4 + j;
            if (gi <= gj) {
                int off = gi * DIMC - (gi * (gi - 1)) / 2 + (gj - gi);
                g[(size_t)b * GRAMD + off] = acc[i][j];
            }
        }
    }
}

// ---------------------------------------------------------------------------
// Fused GEMM + bias + leaky-relu with packed f32x2 FMAs.
// out[b][n] = lrelu(sum_k in[b][k]*W[n][k] + bias[n]).  M = 32 batches.
// Each warp: 4 n x 8 b, lanes slice K (float4 -> 2x f32x2 per operand).
// Block = 256 = 8 warps = 2 n-groups x 4 b-groups -> 8 n, 32 b per block.
// ---------------------------------------------------------------------------
template <int K, int N>
__global__ __launch_bounds__(256)
void gemm_lrelu(const float* __restrict__ in, const float* __restrict__ W,
                const float* __restrict__ bias, float* __restrict__ out)
{
    int t    = threadIdx.x;
    int lane = t & 31;
    int wid  = t >> 5;
    int ng   = wid >> 2;          // 0..1
    int bg   = wid & 3;           // 0..3
    int n0   = blockIdx.x * 8 + ng * 4;
    int b0   = bg * 8;

    unsigned long long acc[4][8];
    #pragma unroll
    for (int i = 0; i < 4; i++)
        #pragma unroll
        for (int j = 0; j < 8; j++) acc[i][j] = 0ull;

    for (int k0 = 0; k0 < K; k0 += 128) {
        int kk = k0 + lane * 4;
        if (kk < K) {   // K % 4 == 0 for all layers
            ulonglong2 w2[4], g2[8];
            #pragma unroll
            for (int i = 0; i < 4; i++)
                w2[i] = *reinterpret_cast<const ulonglong2*>(W + (size_t)(n0 + i) * K + kk);
            #pragma unroll
            for (int j = 0; j < 8; j++)
                g2[j] = *reinterpret_cast<const ulonglong2*>(in + (size_t)(b0 + j) * K + kk);

            #pragma unroll
            for (int i = 0; i < 4; i++) {
                #pragma unroll
                for (int j = 0; j < 8; j++) {
                    ffma2(acc[i][j], w2[i].x, g2[j].x);
                    ffma2(acc[i][j], w2[i].y, g2[j].y);
                }
            }
        }
    }

    // Fold dual lanes, then cross-lane (split-K) butterfly reduction
    float accf[4][8];
    #pragma unroll
    for (int i = 0; i < 4; i++)
        #pragma unroll
        for (int j = 0; j < 8; j++) accf[i][j] = fold_f32x2(acc[i][j]);

    #pragma unroll
    for (int off = 16; off > 0; off >>= 1) {
        #pragma unroll
        for (int i = 0; i < 4; i++)
            #pragma unroll
            for (int j = 0; j < 8; j++)
                accf[i][j] += __shfl_xor_sync(0xffffffffu, accf[i][j], off);
    }

    if (lane == 0) {
        #pragma unroll
        for (int i = 0; i < 4; i++) {
            float bi = bias[n0 + i];
            #pragma unroll
            for (int j = 0; j < 8; j++) {
                float v = accf[i][j] + bi;
                v = (v > 0.0f) ? v : 0.01f * v;
                out[(size_t)(b0 + j) * N + (n0 + i)] = v;
            }
        }
    }
}

// ---------------------------------------------------------------------------
// Layer 3: N=64 -> one block per output neuron (grid=64), warps split batch.
// ---------------------------------------------------------------------------
__global__ __launch_bounds__(256)
void gemm3_lrelu(const float* __restrict__ in, const float* __restrict__ W,
                 const float* __restrict__ bias, float* __restrict__ out)
{
    int n    = blockIdx.x;               // 0..63
    int lane = threadIdx.x & 31;
    int wid  = threadIdx.x >> 5;         // 0..7, 4 batches each

    const float* wrow = W + (size_t)n * N2;

    float acc[4] = {0.f, 0.f, 0.f, 0.f};

    for (int k0 = 0; k0 < N2; k0 += 128) {
        int kk = k0 + lane * 4;
        if (kk < N2) {
            float4 w = *reinterpret_cast<const float4*>(wrow + kk);
            #pragma unroll
            for (int j = 0; j < 4; j++) {
                float4 gv = *reinterpret_cast<const float4*>(in + (size_t)(wid * 4 + j) * N2 + kk);
                acc[j] += w.x * gv.x + w.y * gv.y + w.z * gv.z + w.w * gv.w;
            }
        }
    }

    #pragma unroll
    for (int off = 16; off > 0; off >>= 1)
        #pragma unroll
        for (int j = 0; j < 4; j++)
            acc[j] += __shfl_xor_sync(0xffffffffu, acc[j], off);

    if (lane == 0) {
        float bi = bias[n];
        #pragma unroll
        for (int j = 0; j < 4; j++) {
            float v = acc[j] + bi;
            v = (v > 0.0f) ? v : 0.01f * v;
            out[(size_t)(wid * 4 + j) * N3 + n] = v;
        }
    }
}

// ---------------------------------------------------------------------------
// Final: L2-normalize h3 (per-sample over 64), dot with W4, +b4, sigmoid.
// ---------------------------------------------------------------------------
__global__ void final_kernel(const float* __restrict__ h3, const float* __restrict__ W4,
                             const float* __restrict__ b4, float* __restrict__ out)
{
    int b    = threadIdx.x >> 5;
    int lane = threadIdx.x & 31;

    float v0 = h3[b * 64 + lane * 2];
    float v1 = h3[b * 64 + lane * 2 + 1];

    float ss = v0 * v0 + v1 * v1;
    #pragma unroll
    for (int off = 16; off > 0; off >>= 1)
        ss += __shfl_xor_sync(0xffffffffu, ss, off);

    float denom = fmaxf(sqrtf(ss), 1e-12f);

    float d = v0 * W4[lane * 2] + v1 * W4[lane * 2 + 1];
    #pragma unroll
    for (int off = 16; off > 0; off >>= 1)
        d += __shfl_xor_sync(0xffffffffu, d, off);

    if (lane == 0) {
        float logit = d / denom + b4[0];
        out[b] = 1.0f / (1.0f + expf(-logit));
    }
}

// ---------------------------------------------------------------------------
// Launch.  Inputs (metadata order): x, W1, b1, W2, b2, W3, b3, W4, b4 (fp32)
// ---------------------------------------------------------------------------
extern "C" void kernel_launch(void* const* d_in, const int* in_sizes, int n_in,
                              void* d_out, int out_size)
{
    const float* x  = (const float*)d_in[0];
    const float* W1 = (const float*)d_in[1];
    const float* b1 = (const float*)d_in[2];
    const float* W2 = (const float*)d_in[3];
    const float* b2 = (const float*)d_in[4];
    const float* W3 = (const float*)d_in[5];
    const float* b3 = (const float*)d_in[6];
    const float* W4 = (const float*)d_in[7];
    const float* b4 = (const float*)d_in[8];
    float* out = (float*)d_out;

    float *g, *h1, *h2, *h3;
    cudaGetSymbolAddress((void**)&g,  g_buf);
    cudaGetSymbolAddress((void**)&h1, h1_buf);
    cudaGetSymbolAddress((void**)&h2, h2_buf);
    cudaGetSymbolAddress((void**)&h3, h3_buf);

    gram_kernel<<<dim3(6, BATCH), 256>>>(x, g);
    gemm_lrelu<GRAMD, N1><<<N1 / 8, 256>>>(g,  W1, b1, h1);
    gemm_lrelu<N1,    N2><<<N2 / 8, 256>>>(h1, W2, b2, h2);
    gemm3_lrelu<<<N3, 256>>>(h2, W3, b3, h3);
    final_kernel<<<1, 1024>>>(h3, W4, b4, out);
}